// round 17
// baseline (speedup 1.0000x reference)
#include <cuda_runtime.h>
#include <stdint.h>
#include <math.h>

#define Bb 4
#define Ss 128
#define Nn 512
#define Hh 64
#define Mm 2048
#define XSTR 68      // fp32 tiles (Xtr, P, V) stride
#define WS 72        // pair-permuted split tiles stride (LDS.64 conflict-free)
#define SSTR 132
#define NTH 1024

// smem float offsets
#define F_XTR  0        // fp32 Xtr [128][68]                      8704
#define F_XTXH 8704     // XtxH [128][72] k-pair-permuted          9216
#define F_XTXL 17920    // XtxL [128][72]                          9216
#define F_W    27136    // Gh|Gl|Wvh|Wvl (4608 each); P fp32 overlays [0:8704)
#define F_VSM  45568    // fp32 V [128][68]                        8704
#define F_TAIL 54272    // rb128 cb128 sg64 sb64 sbv64             448
#define F_SC   8704     // scores [128][132] overlay Xtx (dead after phase 2)
#define SMEM_FLOATS 54720   // 218880 B

// k-pair permutation: logical k -> position with (k, k+4) adjacent
__host__ __device__ __forceinline__ int kperm_inv(int p) {
    return (p & ~7) | ((p & 1) << 2) | ((p >> 1) & 3);
}

// ---------------- precomputed operands ----------------
__device__ float g_u[Hh];
__device__ float g_w[Hh];
__device__ float g_c0;
__device__ __align__(16) float g_Wsplit[4*4608];   // Gh | Gl | Wvh | Wvl, [64][72] pair-permuted

__device__ __forceinline__ void tf32x2(float x, uint32_t& h, uint32_t& l) {
    asm("cvt.rna.tf32.f32 %0, %1;" : "=r"(h) : "f"(x));
    float r = x - __uint_as_float(h);
    asm("cvt.rna.tf32.f32 %0, %1;" : "=r"(l) : "f"(r));
}

// Single merged precompute: G computed inline per element; pair-permuted split tiles + bias vectors.
__global__ void precompute_all(const float* __restrict__ Wq, const float* __restrict__ bq,
                               const float* __restrict__ Wk, const float* __restrict__ bk,
                               const float* __restrict__ Wv) {
    int gid = blockIdx.x * blockDim.x + threadIdx.x;
    const float scale = 0.125f;
    if (gid < 2 * 4608) {
        int mat = gid / 4608;            // 0: G (inline), 1: Wv
        int rem = gid % 4608;
        int r = rem / WS, p = rem % WS;
        float v = 0.f;
        if (p < 64) {
            int c = kperm_inv(p);
            if (mat) {
                v = Wv[r*64 + c];
            } else {
                float s = 0.f;
                #pragma unroll 8
                for (int o = 0; o < Hh; o++) s += Wq[o*Hh + c] * Wk[o*Hh + r];
                v = s * scale;
            }
        }
        uint32_t h, l;
        tf32x2(v, h, l);
        g_Wsplit[mat*9216 + rem]        = __uint_as_float(h);
        g_Wsplit[mat*9216 + 4608 + rem] = __uint_as_float(l);
    }
    if (gid < Hh) {
        float s = 0.f, t = 0.f;
        #pragma unroll 8
        for (int o = 0; o < Hh; o++) { s += Wq[o*Hh + gid] * bk[o]; t += Wk[o*Hh + gid] * bq[o]; }
        g_u[gid] = s * scale;
        g_w[gid] = t * scale;
    }
    if (gid == 0) {
        float s = 0.f;
        for (int o = 0; o < Hh; o++) s += bq[o] * bk[o];
        g_c0 = s * scale;
    }
}

// ---------------- mma helpers ----------------
__device__ __forceinline__ void mma8(float c[4], const uint32_t a[4], uint32_t b0, uint32_t b1) {
    asm volatile(
        "mma.sync.aligned.m16n8k8.row.col.f32.tf32.tf32.f32 "
        "{%0,%1,%2,%3}, {%4,%5,%6,%7}, {%8,%9}, {%0,%1,%2,%3};"
        : "+f"(c[0]), "+f"(c[1]), "+f"(c[2]), "+f"(c[3])
        : "r"(a[0]), "r"(a[1]), "r"(a[2]), "r"(a[3]), "r"(b0), "r"(b1));
}

// A fp32 (stride 68, split on the fly), B pair-split (stride 72, LDS.64)
__device__ __forceinline__ void gemm_fp(const float* __restrict__ A,
                                        const float* __restrict__ BH, const float* __restrict__ BL,
                                        int mb, int n0, int lane, float acc[4][4]) {
    const int g = lane >> 2, q = lane & 3;
    const float* ar0 = A + (mb + g) * XSTR + q;
    const float* ar1 = A + (mb + g + 8) * XSTR + q;
    #pragma unroll
    for (int k0 = 0; k0 < 64; k0 += 8) {
        uint32_t ah[4], al[4];
        tf32x2(ar0[k0],   ah[0], al[0]);
        tf32x2(ar1[k0],   ah[1], al[1]);
        tf32x2(ar0[k0+4], ah[2], al[2]);
        tf32x2(ar1[k0+4], ah[3], al[3]);
        #pragma unroll
        for (int nt = 0; nt < 4; nt++) {
            int boff = (n0 + 8*nt + g) * WS + k0 + 2*q;
            float2 bh = *(const float2*)(BH + boff);
            float2 bl = *(const float2*)(BL + boff);
            mma8(acc[nt], ah, __float_as_uint(bh.x), __float_as_uint(bh.y));
            mma8(acc[nt], ah, __float_as_uint(bl.x), __float_as_uint(bl.y));
            mma8(acc[nt], al, __float_as_uint(bh.x), __float_as_uint(bh.y));
        }
    }
}

// A pair-split (stride 72, LDS.64), B pair-split (stride 72, LDS.64)
__device__ __forceinline__ void gemm_pair(const float* __restrict__ AH, const float* __restrict__ AL,
                                          const float* __restrict__ BH, const float* __restrict__ BL,
                                          int mb, int n0, int lane, float acc[4][4]) {
    const int g = lane >> 2, q = lane & 3;
    const float* a0h = AH + (mb + g) * WS + 2*q;
    const float* a1h = AH + (mb + g + 8) * WS + 2*q;
    const float* a0l = AL + (mb + g) * WS + 2*q;
    const float* a1l = AL + (mb + g + 8) * WS + 2*q;
    #pragma unroll
    for (int k0 = 0; k0 < 64; k0 += 8) {
        float2 xh0 = *(const float2*)(a0h + k0);
        float2 xh1 = *(const float2*)(a1h + k0);
        float2 xl0 = *(const float2*)(a0l + k0);
        float2 xl1 = *(const float2*)(a1l + k0);
        uint32_t ah[4] = { __float_as_uint(xh0.x), __float_as_uint(xh1.x),
                           __float_as_uint(xh0.y), __float_as_uint(xh1.y) };
        uint32_t al[4] = { __float_as_uint(xl0.x), __float_as_uint(xl1.x),
                           __float_as_uint(xl0.y), __float_as_uint(xl1.y) };
        #pragma unroll
        for (int nt = 0; nt < 4; nt++) {
            int boff = (n0 + 8*nt + g) * WS + k0 + 2*q;
            float2 bh = *(const float2*)(BH + boff);
            float2 bl = *(const float2*)(BL + boff);
            mma8(acc[nt], ah, __float_as_uint(bh.x), __float_as_uint(bh.y));
            mma8(acc[nt], ah, __float_as_uint(bl.x), __float_as_uint(bl.y));
            mma8(acc[nt], al, __float_as_uint(bh.x), __float_as_uint(bh.y));
        }
    }
}

__device__ __forceinline__ unsigned f2mono(float v) {
    unsigned u = __float_as_uint(v);
    return (u & 0x80000000u) ? ~u : (u | 0x80000000u);
}
__device__ __forceinline__ float mono2f(unsigned k) {
    unsigned u = (k & 0x80000000u) ? (k ^ 0x80000000u) : ~k;
    return __uint_as_float(u);
}

extern __shared__ float smf[];
__global__ void __launch_bounds__(NTH, 1)
fused_align_k(const float* __restrict__ traffic, const float* __restrict__ text,
              const float* __restrict__ Wv, const float* __restrict__ bv,
              const float* __restrict__ gamma, const float* __restrict__ beta,
              const int* __restrict__ topk_p,
              float* __restrict__ out_main, float* __restrict__ out_attn) {
    float* xt_tr = smf + F_XTR;
    float* xtxh  = smf + F_XTXH;
    float* xtxl  = smf + F_XTXL;
    float* Wr    = smf + F_W;       // Gh|Gl|Wvh|Wvl; P fp32 overlays [0:8704)
    float* vsm   = smf + F_VSM;
    float* sc    = smf + F_SC;
    float* rb  = smf + F_TAIL;
    float* cb  = rb + 128;
    float* sg  = cb + 128;
    float* sb  = sg + 64;
    float* sbv = sb + 64;

    const int tid = threadIdx.x;
    const int lane = tid & 31;
    const int wrp = tid >> 5;
    const int m = blockIdx.x;
    const int b = m >> 9;
    const int n = m & (Nn - 1);

    const float* tr_base = traffic + ((size_t)b * Ss * Nn + n) * Hh;
    const float* tx_base = text    + ((size_t)b * Ss * Nn + n) * Hh;

    // ---- Stage 0: weights copy + X tiles (Xtx pair-permuted split) + fused biases ----
    for (int i = tid; i < 4608; i += NTH)
        ((uint4*)Wr)[i] = ((const uint4*)g_Wsplit)[i];
    #pragma unroll
    for (int it = 0; it < 2; it++) {
        int i = tid + it * NTH;
        int r = i >> 4, f = i & 15;
        float4 a  = *(const float4*)(tr_base + (size_t)r * Nn * Hh + f * 4);
        float4 bx = *(const float4*)(tx_base + (size_t)r * Nn * Hh + f * 4);
        *(float4*)(xt_tr + r * XSTR + f * 4) = a;
        // split Xtx -> hi/lo at pair-permuted positions (pairs (k,k+4) adjacent)
        uint32_t h0,l0,h1,l1,h2,l2,h3,l3;
        tf32x2(bx.x,h0,l0); tf32x2(bx.y,h1,l1); tf32x2(bx.z,h2,l2); tf32x2(bx.w,h3,l3);
        int pbase = r * WS + ((f >> 1) << 3) + (f & 1);
        xtxh[pbase + 0] = __uint_as_float(h0);  xtxl[pbase + 0] = __uint_as_float(l0);
        xtxh[pbase + 2] = __uint_as_float(h1);  xtxl[pbase + 2] = __uint_as_float(l1);
        xtxh[pbase + 4] = __uint_as_float(h2);  xtxl[pbase + 4] = __uint_as_float(l2);
        xtxh[pbase + 6] = __uint_as_float(h3);  xtxl[pbase + 6] = __uint_as_float(l3);
        // fused bias partials (16 lanes per row)
        float4 uu = *(const float4*)(g_u + f * 4);
        float4 ww = *(const float4*)(g_w + f * 4);
        float pr = a.x*uu.x + a.y*uu.y + a.z*uu.z + a.w*uu.w;
        float pc = bx.x*ww.x + bx.y*ww.y + bx.z*ww.z + bx.w*ww.w;
        #pragma unroll
        for (int o = 8; o > 0; o >>= 1) {
            pr += __shfl_xor_sync(0xffffffffu, pr, o);
            pc += __shfl_xor_sync(0xffffffffu, pc, o);
        }
        if (f == 0) { rb[r] = pr + g_c0; cb[r] = pc; }
    }
    if (tid < 64) { sg[tid] = gamma[tid]; sb[tid] = beta[tid]; sbv[tid] = bv[tid]; }
    __syncthreads();

    const int g = lane >> 2, q = lane & 3;

    // ---- Phase 1: P (warps 0-15) / V (warps 16-31) ----
    float accPV[4][4];
    #pragma unroll
    for (int i = 0; i < 4; i++)
        #pragma unroll
        for (int j = 0; j < 4; j++) accPV[i][j] = 0.f;
    {
        int w2 = (wrp < 16) ? wrp : (wrp - 16);
        int mb = (w2 >> 1) * 16, n0 = (w2 & 1) * 32;
        if (wrp < 16) {
            gemm_fp(xt_tr, Wr, Wr + 4608, mb, n0, lane, accPV);               // P = Xtr @ G^T
            // P store ordering only involves P-warps (store hits Wr[0:8704) = G region only)
            asm volatile("bar.sync 1, 512;" ::: "memory");
            #pragma unroll
            for (int nt = 0; nt < 4; nt++) {
                int col = n0 + 8*nt + 2*q;
                float2 o0 = { accPV[nt][0], accPV[nt][1] };
                float2 o1 = { accPV[nt][2], accPV[nt][3] };
                *(float2*)(Wr + (mb + g) * XSTR + col)     = o0;
                *(float2*)(Wr + (mb + g + 8) * XSTR + col) = o1;
            }
        } else {
            gemm_pair(xtxh, xtxl, Wr + 9216, Wr + 13824, mb, n0, lane, accPV); // V
            #pragma unroll
            for (int nt = 0; nt < 4; nt++) {
                int col = n0 + 8*nt + 2*q;
                float2 o0 = { accPV[nt][0] + sbv[col], accPV[nt][1] + sbv[col+1] };
                float2 o1 = { accPV[nt][2] + sbv[col], accPV[nt][3] + sbv[col+1] };
                *(float2*)(vsm + (mb + g) * XSTR + col)     = o0;
                *(float2*)(vsm + (mb + g + 8) * XSTR + col) = o1;
            }
        }
    }
    __syncthreads();        // P + V visible

    // ---- Phase 2: S = P @ Xtx^T (A fp32 on-fly, B pair-split LDS.64) ----
    float accS[4][4];
    #pragma unroll
    for (int i = 0; i < 4; i++)
        #pragma unroll
        for (int j = 0; j < 4; j++) accS[i][j] = 0.f;
    const int smb = (wrp >> 2) * 16, sn0 = (wrp & 3) * 32;
    gemm_fp(Wr, xtxh, xtxl, smb, sn0, lane, accS);
    __syncthreads();        // Xtx reads done -> safe to overlay scores
    #pragma unroll
    for (int nt = 0; nt < 4; nt++) {
        int col = sn0 + 8*nt + 2*q;
        float2 o0 = { accS[nt][0], accS[nt][1] };
        float2 o1 = { accS[nt][2], accS[nt][3] };
        *(float2*)(sc + (smb + g) * SSTR + col)     = o0;
        *(float2*)(sc + (smb + g + 8) * SSTR + col) = o1;
    }
    __syncthreads();

    // ---- Stage 3 (identical to R14/R16): minimal exact top-k + post-hoc list AV ----
    int kk = 16;
    if (topk_p) { kk = topk_p[0]; if (kk < 1) kk = 1; if (kk > 32) kk = 32; }

    const int r0 = wrp * 4;
    float* attn_base = out_attn + (size_t)m * Ss * Ss;
    const unsigned FULL = 0xffffffffu;

    #pragma unroll
    for (int rp = 0; rp < 2; rp++) {
        const int sA = r0 + 2*rp;
        float o[2][4];
        unsigned kx[2][4];
        unsigned s0[2], s1[2], s2[2], s3[2];
        #pragma unroll
        for (int j = 0; j < 2; j++) {
            const int s = sA + j;
            float4 sv  = *(const float4*)(sc + s * SSTR + 4 * lane);
            float4 cbv = *(const float4*)(cb + 4 * lane);
            const float rbias = rb[s];
            o[j][0] = sv.x + rbias + cbv.x;
            o[j][1] = sv.y + rbias + cbv.y;
            o[j][2] = sv.z + rbias + cbv.z;
            o[j][3] = sv.w + rbias + cbv.w;
            #pragma unroll
            for (int t = 0; t < 4; t++) kx[j][t] = f2mono(o[j][t]);
            unsigned t0 = kx[j][0], t1 = kx[j][1], t2 = kx[j][2], t3 = kx[j][3], u;
            u = max(t0,t1); t1 = min(t0,t1); t0 = u;
            u = max(t2,t3); t3 = min(t2,t3); t2 = u;
            u = max(t0,t2); t2 = min(t0,t2); t0 = u;
            u = max(t1,t3); t3 = min(t1,t3); t1 = u;
            u = max(t1,t2); t2 = min(t1,t2); t1 = u;
            s0[j] = t0; s1[j] = t1; s2[j] = t2; s3[j] = t3;
        }

        unsigned maxk[2] = {0, 0}, thrk[2] = {0, 0};
        for (int it = 0; it < kk; ++it) {
            unsigned mw0 = __reduce_max_sync(FULL, s0[0]);
            unsigned mw1 = __reduce_max_sync(FULL, s0[1]);
            unsigned bl0 = __ballot_sync(FULL, s0[0] == mw0);
            unsigned bl1 = __ballot_sync(FULL, s0[1] == mw1);
            if (it == 0) { maxk[0] = mw0; maxk[1] = mw1; }
            thrk[0] = mw0; thrk[1] = mw1;
            if (lane == __ffs(bl0) - 1) { s0[0] = s1[0]; s1[0] = s2[0]; s2[0] = s3[0]; s3[0] = 0; }
            if (lane == __ffs(bl1) - 1) { s0[1] = s1[1]; s1[1] = s2[1]; s2[1] = s3[1]; s3[1] = 0; }
        }

        float maxv[2], z[2], inv[2], st[2][4];
        #pragma unroll
        for (int j = 0; j < 2; j++) {
            maxv[j] = mono2f(maxk[j]);
            #pragma unroll
            for (int t = 0; t < 4; t++)
                st[j][t] = (kx[j][t] >= thrk[j]) ? __expf(o[j][t] - maxv[j]) : 0.f;
            z[j] = st[j][0] + st[j][1] + st[j][2] + st[j][3];
        }
        #pragma unroll
        for (int off = 16; off > 0; off >>= 1) {
            z[0] += __shfl_xor_sync(FULL, z[0], off);
            z[1] += __shfl_xor_sync(FULL, z[1], off);
        }
        #pragma unroll
        for (int j = 0; j < 2; j++) {
            inv[j] = 1.0f / z[j];
            #pragma unroll
            for (int t = 0; t < 4; t++) st[j][t] *= inv[j];
            float4 sv4; sv4.x = st[j][0]; sv4.y = st[j][1]; sv4.z = st[j][2]; sv4.w = st[j][3];
            *(float4*)(attn_base + (size_t)(sA + j) * Ss + 4 * lane) = sv4;
        }

        int cnt[2];
        #pragma unroll
        for (int j = 0; j < 2; j++) {
            unsigned b0 = __ballot_sync(FULL, kx[j][0] >= thrk[j]);
            unsigned b1 = __ballot_sync(FULL, kx[j][1] >= thrk[j]);
            unsigned b2 = __ballot_sync(FULL, kx[j][2] >= thrk[j]);
            unsigned b3 = __ballot_sync(FULL, kx[j][3] >= thrk[j]);
            unsigned mbm = (1u << lane) - 1u;
            int off = __popc(b0 & mbm) + __popc(b1 & mbm) + __popc(b2 & mbm) + __popc(b3 & mbm);
            float2* row = (float2*)(sc + (sA + j) * SSTR);
            if (kx[j][0] >= thrk[j]) { row[off] = make_float2(st[j][0], __int_as_float(4*lane + 0)); off++; }
            if (kx[j][1] >= thrk[j]) { row[off] = make_float2(st[j][1], __int_as_float(4*lane + 1)); off++; }
            if (kx[j][2] >= thrk[j]) { row[off] = make_float2(st[j][2], __int_as_float(4*lane + 2)); off++; }
            if (kx[j][3] >= thrk[j]) { row[off] = make_float2(st[j][3], __int_as_float(4*lane + 3)); }
            cnt[j] = __popc(b0) + __popc(b1) + __popc(b2) + __popc(b3);
            if (cnt[j] > 64) cnt[j] = 64;
        }
        __syncwarp();

        float a0[2] = {0.f, 0.f}, a1[2] = {0.f, 0.f};
        const float2* rowA = (const float2*)(sc + sA * SSTR);
        const float2* rowB = (const float2*)(sc + (sA + 1) * SSTR);
        int cmax = cnt[0] > cnt[1] ? cnt[0] : cnt[1];
        for (int i2 = 0; i2 < cmax; i2++) {
            if (i2 < cnt[0]) {
                float2 pv = rowA[i2];
                const float* vr = vsm + __float_as_int(pv.y) * XSTR;
                a0[0] += pv.x * vr[lane];
                a1[0] += pv.x * vr[lane + 32];
            }
            if (i2 < cnt[1]) {
                float2 pv = rowB[i2];
                const float* vr = vsm + __float_as_int(pv.y) * XSTR;
                a0[1] += pv.x * vr[lane];
                a1[1] += pv.x * vr[lane + 32];
            }
        }

        float rr0[2], rr1[2], sm1[2];
        #pragma unroll
        for (int j = 0; j < 2; j++) {
            rr0[j] = a0[j] + xt_tr[(sA + j) * XSTR + lane];
            rr1[j] = a1[j] + xt_tr[(sA + j) * XSTR + lane + 32];
            sm1[j] = rr0[j] + rr1[j];
        }
        #pragma unroll
        for (int off = 16; off > 0; off >>= 1) {
            sm1[0] += __shfl_xor_sync(FULL, sm1[0], off);
            sm1[1] += __shfl_xor_sync(FULL, sm1[1], off);
        }
        float d0[2], d1[2], sq[2];
        #pragma unroll
        for (int j = 0; j < 2; j++) {
            float mu = sm1[j] * (1.0f / 64.0f);
            d0[j] = rr0[j] - mu; d1[j] = rr1[j] - mu;
            sq[j] = d0[j]*d0[j] + d1[j]*d1[j];
        }
        #pragma unroll
        for (int off = 16; off > 0; off >>= 1) {
            sq[0] += __shfl_xor_sync(FULL, sq[0], off);
            sq[1] += __shfl_xor_sync(FULL, sq[1], off);
        }
        #pragma unroll
        for (int j = 0; j < 2; j++) {
            float inv_sd = rsqrtf(sq[j] * (1.0f / 64.0f) + 1e-5f);
            float* ob = out_main + (((size_t)(b * Ss + sA + j)) * Nn + n) * Hh;
            ob[lane]      = d0[j] * inv_sd * sg[lane]      + sb[lane];
            ob[lane + 32] = d1[j] * inv_sd * sg[lane + 32] + sb[lane + 32];
        }
    }
}

extern "C" void kernel_launch(void* const* d_in, const int* in_sizes, int n_in,
                              void* d_out, int out_size) {
    const float* traffic = (const float*)d_in[0];
    const float* text    = (const float*)d_in[1];
    const float* Wq      = (const float*)d_in[2];
    const float* bq      = (const float*)d_in[3];
    const float* Wk      = (const float*)d_in[4];
    const float* bk      = (const float*)d_in[5];
    const float* Wv      = (const float*)d_in[6];
    const float* bv      = (const float*)d_in[7];
    const float* gamma   = (const float*)d_in[8];
    const float* beta    = (const float*)d_in[9];
    const int*   topk    = (n_in > 10) ? (const int*)d_in[10] : nullptr;

    float* out  = (float*)d_out;
    float* attn = out + (size_t)Bb * Ss * Nn * Hh;

    size_t smem = (size_t)SMEM_FLOATS * sizeof(float);   // 218880 B
    cudaFuncSetAttribute(fused_align_k, cudaFuncAttributeMaxDynamicSharedMemorySize, (int)smem);

    precompute_all<<<40, 256>>>(Wq, bq, Wk, bk, Wv);
    fused_align_k<<<Mm, NTH, smem>>>(traffic, text, Wv, bv, gamma, beta, topk, out, attn);
}